// round 15
// baseline (speedup 1.0000x reference)
#include <cuda_runtime.h>
#include <math.h>

#define D 64
#define TWOD 128
#define RD 256            // RANK*D
#define W1S 68            // padded stride for W1 rows (conflict-free LDS.128 both ways)
#define WARPS 8
#define THREADS 256
#define RB 5              // rows per warp
#define SLOT 384          // per-row scratch: A[128]=x|v->g_lo->du, B[128]=h, C[128]=g_hi

// W2 stored stride-128 with XOR chunk swizzle
#define SMEM_FLOATS (TWOD*W1S + RD*TWOD + TWOD + RD + WARPS*RB*SLOT)

typedef unsigned long long ull;

__device__ __forceinline__ ull pack2(float lo, float hi) {
    ull r; asm("mov.b64 %0, {%1, %2};" : "=l"(r) : "f"(lo), "f"(hi)); return r;
}
__device__ __forceinline__ float2 unpack2(ull v) {
    float2 f; asm("mov.b64 {%0, %1}, %2;" : "=f"(f.x), "=f"(f.y) : "l"(v)); return f;
}
__device__ __forceinline__ ull ffma2(ull a, ull b, ull c) {
    ull d; asm("fma.rn.f32x2 %0, %1, %2, %3;" : "=l"(d) : "l"(a), "l"(b), "l"(c)); return d;
}
__device__ __forceinline__ float hadd2(ull v) { float2 f = unpack2(v); return f.x + f.y; }

__device__ __forceinline__ float my_tanh(float x) {
    float xc = fminf(fmaxf(x, -10.0f), 10.0f);
    float e = __expf(2.0f * xc);
    return __fdividef(e - 1.0f, e + 1.0f);
}

__global__ __launch_bounds__(THREADS, 1)
void geognn_grad_kernel(const float* __restrict__ input,
                        const float* __restrict__ W1, const float* __restrict__ b1,
                        const float* __restrict__ W2, const float* __restrict__ b2,
                        float* __restrict__ out, int n)
{
    extern __shared__ float smem[];
    float* W1s = smem;                 // [128][68]
    float* W2s = W1s + TWOD * W1S;     // [256][128], chunk k4 stored at k4^(j&31)
    float* b1s = W2s + RD * TWOD;      // [128]
    float* b2s = b1s + TWOD;           // [256]
    float* scr = b2s + RD;

    const int tid = threadIdx.x;
    const int w   = tid >> 5;
    const int l   = tid & 31;

    // ---- cooperative weight staging ----
    {
        const float4* W1v = (const float4*)W1;
        for (int i = tid; i < TWOD * (D / 4); i += THREADS) {
            int j = i >> 4, k4 = i & 15;
            *(float4*)(W1s + j * W1S + 4 * k4) = W1v[i];
        }
        const float4* W2v = (const float4*)W2;
        for (int i = tid; i < RD * (TWOD / 4); i += THREADS) {
            int j = i >> 5, k4 = i & 31;
            *(float4*)(W2s + j * TWOD + 4 * (k4 ^ (j & 31))) = W2v[i];
        }
        for (int i = tid; i < TWOD; i += THREADS) b1s[i] = b1[i];
        for (int i = tid; i < RD;   i += THREADS) b2s[i] = b2[i];
    }
    __syncthreads();

    float* slot[RB];
    #pragma unroll
    for (int r = 0; r < RB; r++) slot[r] = scr + (w * RB + r) * SLOT;

    const int gw = blockIdx.x * WARPS + w;
    const long stride = (long)gridDim.x * WARPS * RB;

    for (long base = (long)gw * RB; base < n; base += stride) {
        __syncwarp();

        int rows[RB];
        #pragma unroll
        for (int r = 0; r < RB; r++) {
            long rr = base + r;
            rows[r] = (rr < n) ? (int)rr : (n - 1);
        }

        // ---- load x|v into A ----
        #pragma unroll
        for (int r = 0; r < RB; r++)
            ((float4*)slot[r])[l] = ((const float4*)(input + (size_t)rows[r] * TWOD))[l];
        __syncwarp();

        // ==== fwd1: h = tanh(W1 @ x + b1), lane owns j = l+32p — packed over k ====
        {
            ull a2[RB][4];
            #pragma unroll
            for (int r = 0; r < RB; r++)
                #pragma unroll
                for (int p = 0; p < 4; p++) a2[r][p] = pack2(b1s[l + 32 * p], 0.0f);

            const float* p0 = W1s + (l)      * W1S;
            const float* p1 = W1s + (l + 32) * W1S;
            const float* p2 = W1s + (l + 64) * W1S;
            const float* p3 = W1s + (l + 96) * W1S;
            #pragma unroll 4
            for (int k = 0; k < D; k += 4) {
                ulonglong2 q0 = *(const ulonglong2*)(p0 + k);
                ulonglong2 q1 = *(const ulonglong2*)(p1 + k);
                ulonglong2 q2 = *(const ulonglong2*)(p2 + k);
                ulonglong2 q3 = *(const ulonglong2*)(p3 + k);
                #pragma unroll
                for (int r = 0; r < RB; r++) {
                    ulonglong2 xk = *(const ulonglong2*)(slot[r] + k);   // broadcast
                    a2[r][0] = ffma2(q0.x, xk.x, a2[r][0]); a2[r][0] = ffma2(q0.y, xk.y, a2[r][0]);
                    a2[r][1] = ffma2(q1.x, xk.x, a2[r][1]); a2[r][1] = ffma2(q1.y, xk.y, a2[r][1]);
                    a2[r][2] = ffma2(q2.x, xk.x, a2[r][2]); a2[r][2] = ffma2(q2.y, xk.y, a2[r][2]);
                    a2[r][3] = ffma2(q3.x, xk.x, a2[r][3]); a2[r][3] = ffma2(q3.y, xk.y, a2[r][3]);
                }
            }
            #pragma unroll
            for (int r = 0; r < RB; r++) {
                slot[r][128 + l]      = my_tanh(hadd2(a2[r][0]));
                slot[r][128 + l + 32] = my_tanh(hadd2(a2[r][1]));
                slot[r][128 + l + 64] = my_tanh(hadd2(a2[r][2]));
                slot[r][128 + l + 96] = my_tanh(hadd2(a2[r][3]));
            }
        }
        __syncwarp();

        // ==== fwd2: m = W2 @ h + b2, lane owns j = l+32t — packed over k ====
        ull mac2[8][RB];
        #pragma unroll
        for (int t = 0; t < 8; t++)
            #pragma unroll
            for (int r = 0; r < RB; r++) mac2[t][r] = pack2(b2s[l + 32 * t], 0.0f);

        #pragma unroll 2
        for (int k4 = 0; k4 < 32; k4++) {
            const int koff = 4 * (k4 ^ l);
            ulonglong2 hk2[RB];
            #pragma unroll
            for (int r = 0; r < RB; r++) hk2[r] = *(const ulonglong2*)(slot[r] + 128 + 4 * k4);
            #pragma unroll
            for (int t = 0; t < 8; t++) {
                ulonglong2 q = *(const ulonglong2*)(W2s + (l + 32 * t) * TWOD + koff);
                #pragma unroll
                for (int r = 0; r < RB; r++) {
                    mac2[t][r] = ffma2(q.x, hk2[r].x, mac2[t][r]);
                    mac2[t][r] = ffma2(q.y, hk2[r].y, mac2[t][r]);
                }
            }
        }

        // ==== middle: wm (regs), y, dv, g — per row ====
        #pragma unroll
        for (int r = 0; r < RB; r++) {
            float wm[8], vi[8];
            #pragma unroll
            for (int t = 0; t < 8; t++) wm[t] = my_tanh(hadd2(mac2[t][r]));
            #pragma unroll
            for (int t = 0; t < 8; t++) vi[t] = slot[r][64 + (l >> 2) + 8 * t];

            float y = 0.f;
            #pragma unroll
            for (int t = 0; t < 8; t++) y = fmaf(vi[t], wm[t], y);
            y += __shfl_xor_sync(0xffffffffu, y, 4);
            y += __shfl_xor_sync(0xffffffffu, y, 8);
            y += __shfl_xor_sync(0xffffffffu, y, 16);   // y = y[l&3] on all lanes

            float* outrow = out + (size_t)rows[r] * TWOD;
            #pragma unroll
            for (int t = 0; t < 8; t++) {
                float p = y * wm[t];
                p += __shfl_xor_sync(0xffffffffu, p, 1);
                p += __shfl_xor_sync(0xffffffffu, p, 2);
                if ((l & 3) == 0) outrow[D + (l >> 2) + 8 * t] = -2.0f * p;
                float g = 2.0f * y * vi[t] * (1.0f - wm[t] * wm[t]);
                if (t < 4) slot[r][l + 32 * t]             = g;   // g_lo over dead x|v
                else       slot[r][256 + l + 32 * t - 128] = g;   // g_hi in C
            }
        }
        __syncwarp();

        // ==== bwd W2: dh[k] = sum_j W2[j][k]*g[j]; lane owns k = 4l..4l+3 — packed over k ====
        {
            ull dacc2[RB][2];
            #pragma unroll
            for (int r = 0; r < RB; r++) { dacc2[r][0] = 0ull; dacc2[r][1] = 0ull; }

            #pragma unroll 2
            for (int jq = 0; jq < 64; jq++) {
                const int j  = 4 * jq;
                const int jb = j & 31;
                const float* wp = W2s + j * TWOD;
                ulonglong2 q0 = *(const ulonglong2*)(wp            + 4 * (l ^ (jb)));
                ulonglong2 q1 = *(const ulonglong2*)(wp + TWOD     + 4 * (l ^ (jb + 1)));
                ulonglong2 q2 = *(const ulonglong2*)(wp + 2 * TWOD + 4 * (l ^ (jb + 2)));
                ulonglong2 q3 = *(const ulonglong2*)(wp + 3 * TWOD + 4 * (l ^ (jb + 3)));
                const int goff = (jq < 32) ? j : (256 + j - 128);
                #pragma unroll
                for (int r = 0; r < RB; r++) {
                    float4 gq = *(const float4*)(slot[r] + goff);    // broadcast
                    ull gx = pack2(gq.x, gq.x), gy = pack2(gq.y, gq.y);
                    ull gz = pack2(gq.z, gq.z), gw = pack2(gq.w, gq.w);
                    dacc2[r][0] = ffma2(gx, q0.x, dacc2[r][0]);
                    dacc2[r][0] = ffma2(gy, q1.x, dacc2[r][0]);
                    dacc2[r][0] = ffma2(gz, q2.x, dacc2[r][0]);
                    dacc2[r][0] = ffma2(gw, q3.x, dacc2[r][0]);
                    dacc2[r][1] = ffma2(gx, q0.y, dacc2[r][1]);
                    dacc2[r][1] = ffma2(gy, q1.y, dacc2[r][1]);
                    dacc2[r][1] = ffma2(gz, q2.y, dacc2[r][1]);
                    dacc2[r][1] = ffma2(gw, q3.y, dacc2[r][1]);
                }
            }
            __syncwarp();   // all g reads done before du overwrites A
            #pragma unroll
            for (int r = 0; r < RB; r++) {
                float2 dA = unpack2(dacc2[r][0]);
                float2 dB = unpack2(dacc2[r][1]);
                float4 hk = *(const float4*)(slot[r] + 128 + 4 * l);
                float4 du;
                du.x = dA.x * (1.0f - hk.x * hk.x);
                du.y = dA.y * (1.0f - hk.y * hk.y);
                du.z = dB.x * (1.0f - hk.z * hk.z);
                du.w = dB.y * (1.0f - hk.w * hk.w);
                *(float4*)(slot[r] + 4 * l) = du;     // du over g_lo
            }
        }
        __syncwarp();

        // ==== bwd W1: dx[i] = sum_j W1[j][i]*du[j]; lane owns i = 2l,2l+1 — packed over i ====
        {
            ull xo2[RB];
            #pragma unroll
            for (int r = 0; r < RB; r++) xo2[r] = 0ull;
            const float* c1 = W1s + 2 * l;
            #pragma unroll 2
            for (int jq = 0; jq < 32; jq++) {
                const int j = 4 * jq;
                ull c0 = *(const ull*)(c1 + (j)     * W1S);
                ull ca = *(const ull*)(c1 + (j + 1) * W1S);
                ull cb = *(const ull*)(c1 + (j + 2) * W1S);
                ull cc = *(const ull*)(c1 + (j + 3) * W1S);
                #pragma unroll
                for (int r = 0; r < RB; r++) {
                    float4 dq = *(const float4*)(slot[r] + j);   // du broadcast
                    xo2[r] = ffma2(pack2(dq.x, dq.x), c0, xo2[r]);
                    xo2[r] = ffma2(pack2(dq.y, dq.y), ca, xo2[r]);
                    xo2[r] = ffma2(pack2(dq.z, dq.z), cb, xo2[r]);
                    xo2[r] = ffma2(pack2(dq.w, dq.w), cc, xo2[r]);
                }
            }
            #pragma unroll
            for (int r = 0; r < RB; r++) {
                float2 xr = unpack2(xo2[r]);
                *(float2*)(out + (size_t)rows[r] * TWOD + 2 * l) = xr;
            }
        }
    }
}

extern "C" void kernel_launch(void* const* d_in, const int* in_sizes, int n_in,
                              void* d_out, int out_size) {
    // inputs: t(1), input_(N*128), W1(128*64), b1(128), W2(256*128), b2(256)
    const float* input = (const float*)d_in[1];
    const float* W1    = (const float*)d_in[2];
    const float* b1    = (const float*)d_in[3];
    const float* W2    = (const float*)d_in[4];
    const float* b2    = (const float*)d_in[5];
    float* out = (float*)d_out;
    const int n = in_sizes[1] / TWOD;

    static_assert(SMEM_FLOATS * 4 < 232448, "smem budget");

    int dev = 0;
    cudaGetDevice(&dev);
    int nsm = 148;
    cudaDeviceGetAttribute(&nsm, cudaDevAttrMultiProcessorCount, dev);

    cudaFuncSetAttribute(geognn_grad_kernel,
                         cudaFuncAttributeMaxDynamicSharedMemorySize,
                         SMEM_FLOATS * (int)sizeof(float));

    geognn_grad_kernel<<<nsm, THREADS, SMEM_FLOATS * (int)sizeof(float)>>>(
        input, W1, b1, W2, b2, out, n);
}

// round 16
// speedup vs baseline: 1.0002x; 1.0002x over previous
#include <cuda_runtime.h>
#include <math.h>

#define D 64
#define TWOD 128
#define RD 256            // RANK*D
#define W1S 68            // padded stride for W1 rows (conflict-free LDS.128 both ways)
#define WARPS 8
#define THREADS 256
#define RB 5              // rows per warp
#define SLOT 384          // per-row scratch: A[128]=x|v->g_lo->du, B[128]=h, C[128]=g_hi

// W2 stored stride-128 with XOR chunk swizzle
#define SMEM_FLOATS (TWOD*W1S + RD*TWOD + TWOD + RD + WARPS*RB*SLOT)

typedef unsigned long long ull;

__device__ __forceinline__ ull pack2(float lo, float hi) {
    ull r; asm("mov.b64 %0, {%1, %2};" : "=l"(r) : "f"(lo), "f"(hi)); return r;
}
__device__ __forceinline__ float2 unpack2(ull v) {
    float2 f; asm("mov.b64 {%0, %1}, %2;" : "=f"(f.x), "=f"(f.y) : "l"(v)); return f;
}
__device__ __forceinline__ ull ffma2(ull a, ull b, ull c) {
    ull d; asm("fma.rn.f32x2 %0, %1, %2, %3;" : "=l"(d) : "l"(a), "l"(b), "l"(c)); return d;
}
__device__ __forceinline__ float hadd2(ull v) { float2 f = unpack2(v); return f.x + f.y; }

__device__ __forceinline__ float my_tanh(float x) {
    float xc = fminf(fmaxf(x, -10.0f), 10.0f);
    float e = __expf(2.0f * xc);
    return __fdividef(e - 1.0f, e + 1.0f);
}

__global__ __launch_bounds__(THREADS, 1)
void geognn_grad_kernel(const float* __restrict__ input,
                        const float* __restrict__ W1, const float* __restrict__ b1,
                        const float* __restrict__ W2, const float* __restrict__ b2,
                        float* __restrict__ out, int n)
{
    extern __shared__ float smem[];
    float* W1s = smem;                 // [128][68]
    float* W2s = W1s + TWOD * W1S;     // [256][128], chunk k4 stored at k4^(j&31)
    float* b1s = W2s + RD * TWOD;      // [128]
    float* b2s = b1s + TWOD;           // [256]
    float* scr = b2s + RD;

    const int tid = threadIdx.x;
    const int w   = tid >> 5;
    const int l   = tid & 31;

    // ---- cooperative weight staging ----
    {
        const float4* W1v = (const float4*)W1;
        for (int i = tid; i < TWOD * (D / 4); i += THREADS) {
            int j = i >> 4, k4 = i & 15;
            *(float4*)(W1s + j * W1S + 4 * k4) = W1v[i];
        }
        const float4* W2v = (const float4*)W2;
        for (int i = tid; i < RD * (TWOD / 4); i += THREADS) {
            int j = i >> 5, k4 = i & 31;
            *(float4*)(W2s + j * TWOD + 4 * (k4 ^ (j & 31))) = W2v[i];
        }
        for (int i = tid; i < TWOD; i += THREADS) b1s[i] = b1[i];
        for (int i = tid; i < RD;   i += THREADS) b2s[i] = b2[i];
    }
    __syncthreads();

    float* slot[RB];
    #pragma unroll
    for (int r = 0; r < RB; r++) slot[r] = scr + (w * RB + r) * SLOT;

    const int gw = blockIdx.x * WARPS + w;
    const long stride = (long)gridDim.x * WARPS * RB;

    for (long base = (long)gw * RB; base < n; base += stride) {
        __syncwarp();

        int rows[RB];
        #pragma unroll
        for (int r = 0; r < RB; r++) {
            long rr = base + r;
            rows[r] = (rr < n) ? (int)rr : (n - 1);
        }

        // ---- load x|v into A ----
        #pragma unroll
        for (int r = 0; r < RB; r++)
            ((float4*)slot[r])[l] = ((const float4*)(input + (size_t)rows[r] * TWOD))[l];
        __syncwarp();

        // ==== fwd1: h = tanh(W1 @ x + b1), lane owns j = l+32p — packed over k ====
        {
            ull a2[RB][4];
            #pragma unroll
            for (int r = 0; r < RB; r++)
                #pragma unroll
                for (int p = 0; p < 4; p++) a2[r][p] = pack2(b1s[l + 32 * p], 0.0f);

            const float* p0 = W1s + (l)      * W1S;
            const float* p1 = W1s + (l + 32) * W1S;
            const float* p2 = W1s + (l + 64) * W1S;
            const float* p3 = W1s + (l + 96) * W1S;
            #pragma unroll 4
            for (int k = 0; k < D; k += 4) {
                ulonglong2 q0 = *(const ulonglong2*)(p0 + k);
                ulonglong2 q1 = *(const ulonglong2*)(p1 + k);
                ulonglong2 q2 = *(const ulonglong2*)(p2 + k);
                ulonglong2 q3 = *(const ulonglong2*)(p3 + k);
                #pragma unroll
                for (int r = 0; r < RB; r++) {
                    ulonglong2 xk = *(const ulonglong2*)(slot[r] + k);   // broadcast
                    a2[r][0] = ffma2(q0.x, xk.x, a2[r][0]); a2[r][0] = ffma2(q0.y, xk.y, a2[r][0]);
                    a2[r][1] = ffma2(q1.x, xk.x, a2[r][1]); a2[r][1] = ffma2(q1.y, xk.y, a2[r][1]);
                    a2[r][2] = ffma2(q2.x, xk.x, a2[r][2]); a2[r][2] = ffma2(q2.y, xk.y, a2[r][2]);
                    a2[r][3] = ffma2(q3.x, xk.x, a2[r][3]); a2[r][3] = ffma2(q3.y, xk.y, a2[r][3]);
                }
            }
            #pragma unroll
            for (int r = 0; r < RB; r++) {
                slot[r][128 + l]      = my_tanh(hadd2(a2[r][0]));
                slot[r][128 + l + 32] = my_tanh(hadd2(a2[r][1]));
                slot[r][128 + l + 64] = my_tanh(hadd2(a2[r][2]));
                slot[r][128 + l + 96] = my_tanh(hadd2(a2[r][3]));
            }
        }
        __syncwarp();

        // ==== fwd2: m = W2 @ h + b2, lane owns j = l+32t — packed over k ====
        ull mac2[8][RB];
        #pragma unroll
        for (int t = 0; t < 8; t++)
            #pragma unroll
            for (int r = 0; r < RB; r++) mac2[t][r] = pack2(b2s[l + 32 * t], 0.0f);

        #pragma unroll 2
        for (int k4 = 0; k4 < 32; k4++) {
            const int koff = 4 * (k4 ^ l);
            ulonglong2 hk2[RB];
            #pragma unroll
            for (int r = 0; r < RB; r++) hk2[r] = *(const ulonglong2*)(slot[r] + 128 + 4 * k4);
            #pragma unroll
            for (int t = 0; t < 8; t++) {
                ulonglong2 q = *(const ulonglong2*)(W2s + (l + 32 * t) * TWOD + koff);
                #pragma unroll
                for (int r = 0; r < RB; r++) {
                    mac2[t][r] = ffma2(q.x, hk2[r].x, mac2[t][r]);
                    mac2[t][r] = ffma2(q.y, hk2[r].y, mac2[t][r]);
                }
            }
        }

        // ==== middle: wm (regs), y, dv, g — per row ====
        #pragma unroll
        for (int r = 0; r < RB; r++) {
            float wm[8], vi[8];
            #pragma unroll
            for (int t = 0; t < 8; t++) wm[t] = my_tanh(hadd2(mac2[t][r]));
            #pragma unroll
            for (int t = 0; t < 8; t++) vi[t] = slot[r][64 + (l >> 2) + 8 * t];

            float y = 0.f;
            #pragma unroll
            for (int t = 0; t < 8; t++) y = fmaf(vi[t], wm[t], y);
            y += __shfl_xor_sync(0xffffffffu, y, 4);
            y += __shfl_xor_sync(0xffffffffu, y, 8);
            y += __shfl_xor_sync(0xffffffffu, y, 16);   // y = y[l&3] on all lanes

            float* outrow = out + (size_t)rows[r] * TWOD;
            #pragma unroll
            for (int t = 0; t < 8; t++) {
                float p = y * wm[t];
                p += __shfl_xor_sync(0xffffffffu, p, 1);
                p += __shfl_xor_sync(0xffffffffu, p, 2);
                if ((l & 3) == 0) outrow[D + (l >> 2) + 8 * t] = -2.0f * p;
                float g = 2.0f * y * vi[t] * (1.0f - wm[t] * wm[t]);
                if (t < 4) slot[r][l + 32 * t]             = g;   // g_lo over dead x|v
                else       slot[r][256 + l + 32 * t - 128] = g;   // g_hi in C
            }
        }
        __syncwarp();

        // ==== bwd W2: dh[k] = sum_j W2[j][k]*g[j]; lane owns k = 4l..4l+3 — packed over k ====
        {
            ull dacc2[RB][2];
            #pragma unroll
            for (int r = 0; r < RB; r++) { dacc2[r][0] = 0ull; dacc2[r][1] = 0ull; }

            #pragma unroll 2
            for (int jq = 0; jq < 64; jq++) {
                const int j  = 4 * jq;
                const int jb = j & 31;
                const float* wp = W2s + j * TWOD;
                ulonglong2 q0 = *(const ulonglong2*)(wp            + 4 * (l ^ (jb)));
                ulonglong2 q1 = *(const ulonglong2*)(wp + TWOD     + 4 * (l ^ (jb + 1)));
                ulonglong2 q2 = *(const ulonglong2*)(wp + 2 * TWOD + 4 * (l ^ (jb + 2)));
                ulonglong2 q3 = *(const ulonglong2*)(wp + 3 * TWOD + 4 * (l ^ (jb + 3)));
                const int goff = (jq < 32) ? j : (256 + j - 128);
                #pragma unroll
                for (int r = 0; r < RB; r++) {
                    float4 gq = *(const float4*)(slot[r] + goff);    // broadcast
                    ull gx = pack2(gq.x, gq.x), gy = pack2(gq.y, gq.y);
                    ull gz = pack2(gq.z, gq.z), gw = pack2(gq.w, gq.w);
                    dacc2[r][0] = ffma2(gx, q0.x, dacc2[r][0]);
                    dacc2[r][0] = ffma2(gy, q1.x, dacc2[r][0]);
                    dacc2[r][0] = ffma2(gz, q2.x, dacc2[r][0]);
                    dacc2[r][0] = ffma2(gw, q3.x, dacc2[r][0]);
                    dacc2[r][1] = ffma2(gx, q0.y, dacc2[r][1]);
                    dacc2[r][1] = ffma2(gy, q1.y, dacc2[r][1]);
                    dacc2[r][1] = ffma2(gz, q2.y, dacc2[r][1]);
                    dacc2[r][1] = ffma2(gw, q3.y, dacc2[r][1]);
                }
            }
            __syncwarp();   // all g reads done before du overwrites A
            #pragma unroll
            for (int r = 0; r < RB; r++) {
                float2 dA = unpack2(dacc2[r][0]);
                float2 dB = unpack2(dacc2[r][1]);
                float4 hk = *(const float4*)(slot[r] + 128 + 4 * l);
                float4 du;
                du.x = dA.x * (1.0f - hk.x * hk.x);
                du.y = dA.y * (1.0f - hk.y * hk.y);
                du.z = dB.x * (1.0f - hk.z * hk.z);
                du.w = dB.y * (1.0f - hk.w * hk.w);
                *(float4*)(slot[r] + 4 * l) = du;     // du over g_lo
            }
        }
        __syncwarp();

        // ==== bwd W1: dx[i] = sum_j W1[j][i]*du[j]; lane owns i = 2l,2l+1 — packed over i ====
        {
            ull xo2[RB];
            #pragma unroll
            for (int r = 0; r < RB; r++) xo2[r] = 0ull;
            const float* c1 = W1s + 2 * l;
            #pragma unroll 2
            for (int jq = 0; jq < 32; jq++) {
                const int j = 4 * jq;
                ull c0 = *(const ull*)(c1 + (j)     * W1S);
                ull ca = *(const ull*)(c1 + (j + 1) * W1S);
                ull cb = *(const ull*)(c1 + (j + 2) * W1S);
                ull cc = *(const ull*)(c1 + (j + 3) * W1S);
                #pragma unroll
                for (int r = 0; r < RB; r++) {
                    float4 dq = *(const float4*)(slot[r] + j);   // du broadcast
                    xo2[r] = ffma2(pack2(dq.x, dq.x), c0, xo2[r]);
                    xo2[r] = ffma2(pack2(dq.y, dq.y), ca, xo2[r]);
                    xo2[r] = ffma2(pack2(dq.z, dq.z), cb, xo2[r]);
                    xo2[r] = ffma2(pack2(dq.w, dq.w), cc, xo2[r]);
                }
            }
            #pragma unroll
            for (int r = 0; r < RB; r++) {
                float2 xr = unpack2(xo2[r]);
                *(float2*)(out + (size_t)rows[r] * TWOD + 2 * l) = xr;
            }
        }
    }
}

extern "C" void kernel_launch(void* const* d_in, const int* in_sizes, int n_in,
                              void* d_out, int out_size) {
    // inputs: t(1), input_(N*128), W1(128*64), b1(128), W2(256*128), b2(256)
    const float* input = (const float*)d_in[1];
    const float* W1    = (const float*)d_in[2];
    const float* b1    = (const float*)d_in[3];
    const float* W2    = (const float*)d_in[4];
    const float* b2    = (const float*)d_in[5];
    float* out = (float*)d_out;
    const int n = in_sizes[1] / TWOD;

    static_assert(SMEM_FLOATS * 4 < 232448, "smem budget");

    int dev = 0;
    cudaGetDevice(&dev);
    int nsm = 148;
    cudaDeviceGetAttribute(&nsm, cudaDevAttrMultiProcessorCount, dev);

    cudaFuncSetAttribute(geognn_grad_kernel,
                         cudaFuncAttributeMaxDynamicSharedMemorySize,
                         SMEM_FLOATS * (int)sizeof(float));

    geognn_grad_kernel<<<nsm, THREADS, SMEM_FLOATS * (int)sizeof(float)>>>(
        input, W1, b1, W2, b2, out, n);
}